// round 2
// baseline (speedup 1.0000x reference)
#include <cuda_runtime.h>
#include <cuda_fp16.h>
#include <cstdint>

#define BATCH 16
#define SEQ   256
#define DIM   512
#define G4    2048
#define LN_EPS 1e-5f

#define GROUPS 8                  // CTAs per batch
#define NCTA  (BATCH*GROUPS)      // 128
#define TPB   512
#define ROWS_PER_CTA 256
#define ROWS_PER_WARP 16
#define NWARP 16

// ---------------- static device scratch (no allocation allowed) ----------------
__device__ __half  d_whh0h[(size_t)BATCH*G4*DIM];   // 32 MB fp16
__device__ __half  d_w1h  [(size_t)BATCH*G4*DIM];   // 32 MB fp16 (wih1+whh1)
__device__ float   d_pre0 [(size_t)BATCH*SEQ*G4];   // 32 MB: wih0@x + bih0 + bhh0
__device__ float   d_bias1[BATCH*G4];
__device__ float   d_gates[2*BATCH*G4];             // double-buffered per layer
__device__ float2  d_gstat[2*NCTA];                 // per-CTA (sum, sumsq), per layer
__device__ unsigned d_bar [BATCH*32];               // per-batch barrier counters (padded)

// ---------------- prep: fp16 convert, merge layer-1 weights, fold biases, reset ----
__global__ void prep_kernel(const float* __restrict__ whh0,
                            const float* __restrict__ wih1,
                            const float* __restrict__ whh1,
                            const float* __restrict__ bih1,
                            const float* __restrict__ bhh1)
{
    int idx0 = blockIdx.x * blockDim.x + threadIdx.x;
    int stride = gridDim.x * blockDim.x;
    const size_t NW = (size_t)BATCH * G4 * DIM;
    for (size_t i = idx0; i < NW; i += stride) {
        d_whh0h[i] = __float2half_rn(whh0[i]);
        d_w1h[i]   = __float2half_rn(wih1[i] + whh1[i]);
    }
    if (idx0 < BATCH * G4) d_bias1[idx0] = bih1[idx0] + bhh1[idx0];
    if (idx0 < BATCH * 32) d_bar[idx0] = 0u;
}

// ---- SGEMM: d_pre0[b][t][j] = sum_d wih0[b][j][d]*x[b][t][d] + bih0[b][j] + bhh0[b][j]
__global__ void __launch_bounds__(256) gemm_pre0(const float* __restrict__ x,
                                                 const float* __restrict__ wih0,
                                                 const float* __restrict__ bih0,
                                                 const float* __restrict__ bhh0)
{
    __shared__ float As[16][132];
    __shared__ float Bs[16][132];
    const int b  = blockIdx.y;
    const int mt = blockIdx.x & 15;   // j tile (2048/128 = 16)
    const int nt = blockIdx.x >> 4;   // t tile (256/128  = 2)
    const float* A = wih0 + ((size_t)b * G4  + (size_t)mt * 128) * DIM;
    const float* B = x    + ((size_t)b * SEQ + (size_t)nt * 128) * DIM;
    const int tid = threadIdx.x;
    const int tr = tid & 15;          // j-frag selector
    const int tc = tid >> 4;          // t-frag selector

    float acc[8][8];
#pragma unroll
    for (int i = 0; i < 8; i++)
#pragma unroll
        for (int j = 0; j < 8; j++) acc[i][j] = 0.f;

    for (int k0 = 0; k0 < DIM; k0 += 16) {
        __syncthreads();
#pragma unroll
        for (int p = 0; p < 2; p++) {
            int fid = tid + p * 256;
            int row = fid >> 2;
            int kq  = fid & 3;
            float4 va = *(const float4*)(A + (size_t)row * DIM + k0 + kq * 4);
            As[kq*4+0][row] = va.x; As[kq*4+1][row] = va.y;
            As[kq*4+2][row] = va.z; As[kq*4+3][row] = va.w;
            float4 vb = *(const float4*)(B + (size_t)row * DIM + k0 + kq * 4);
            Bs[kq*4+0][row] = vb.x; Bs[kq*4+1][row] = vb.y;
            Bs[kq*4+2][row] = vb.z; Bs[kq*4+3][row] = vb.w;
        }
        __syncthreads();
#pragma unroll
        for (int kk = 0; kk < 16; kk++) {
            float af[8], bf[8];
#pragma unroll
            for (int i = 0; i < 4; i++) {
                af[i]   = As[kk][tr*4 + i];
                af[4+i] = As[kk][64 + tr*4 + i];
                bf[i]   = Bs[kk][tc*4 + i];
                bf[4+i] = Bs[kk][64 + tc*4 + i];
            }
#pragma unroll
            for (int i = 0; i < 8; i++)
#pragma unroll
                for (int j = 0; j < 8; j++)
                    acc[i][j] = fmaf(af[i], bf[j], acc[i][j]);
        }
    }

    float biasv[8];
#pragma unroll
    for (int i = 0; i < 8; i++) {
        int j = mt * 128 + ((i < 4) ? (tr*4 + i) : (64 + tr*4 + (i - 4)));
        biasv[i] = bih0[b * G4 + j] + bhh0[b * G4 + j];
    }
#pragma unroll
    for (int jj = 0; jj < 8; jj++) {
        int t = nt * 128 + ((jj < 4) ? (tc*4 + jj) : (64 + tc*4 + (jj - 4)));
        float* dst = &d_pre0[((size_t)b * SEQ + t) * G4 + mt * 128];
        float4 v0, v1;
        v0.x = acc[0][jj] + biasv[0]; v0.y = acc[1][jj] + biasv[1];
        v0.z = acc[2][jj] + biasv[2]; v0.w = acc[3][jj] + biasv[3];
        v1.x = acc[4][jj] + biasv[4]; v1.y = acc[5][jj] + biasv[5];
        v1.z = acc[6][jj] + biasv[6]; v1.w = acc[7][jj] + biasv[7];
        *(float4*)(dst + tr * 4)      = v0;
        *(float4*)(dst + 64 + tr * 4) = v1;
    }
}

// ---------------- persistent LSTM kernel ----------------
__device__ __forceinline__ float sigmoidf_(float x) {
    return __fdividef(1.f, 1.f + __expf(-x));
}

__device__ __forceinline__ float dot16(uint4 wa, uint4 wb, const float* hf) {
    float acc = 0.f;
    float2 f;
    f = __half22float2(*reinterpret_cast<__half2*>(&wa.x)); acc = fmaf(f.x, hf[0],  acc); acc = fmaf(f.y, hf[1],  acc);
    f = __half22float2(*reinterpret_cast<__half2*>(&wa.y)); acc = fmaf(f.x, hf[2],  acc); acc = fmaf(f.y, hf[3],  acc);
    f = __half22float2(*reinterpret_cast<__half2*>(&wa.z)); acc = fmaf(f.x, hf[4],  acc); acc = fmaf(f.y, hf[5],  acc);
    f = __half22float2(*reinterpret_cast<__half2*>(&wa.w)); acc = fmaf(f.x, hf[6],  acc); acc = fmaf(f.y, hf[7],  acc);
    f = __half22float2(*reinterpret_cast<__half2*>(&wb.x)); acc = fmaf(f.x, hf[8],  acc); acc = fmaf(f.y, hf[9],  acc);
    f = __half22float2(*reinterpret_cast<__half2*>(&wb.y)); acc = fmaf(f.x, hf[10], acc); acc = fmaf(f.y, hf[11], acc);
    f = __half22float2(*reinterpret_cast<__half2*>(&wb.z)); acc = fmaf(f.x, hf[12], acc); acc = fmaf(f.y, hf[13], acc);
    f = __half22float2(*reinterpret_cast<__half2*>(&wb.w)); acc = fmaf(f.x, hf[14], acc); acc = fmaf(f.y, hf[15], acc);
    return acc;
}

// 8-CTA per-batch barrier (release/acquire via L2 atomics)
__device__ __forceinline__ void group_barrier(volatile unsigned* bar, unsigned* epoch, int tid) {
    __syncthreads();
    *epoch += GROUPS;
    unsigned target = *epoch;
    if (tid == 0) {
        __threadfence();
        atomicAdd((unsigned*)bar, 1u);
        while (*bar < target) { }
        __threadfence();
    }
    __syncthreads();
}

__global__ void __launch_bounds__(TPB, 1)
lstm_kernel(const float* __restrict__ lnw, const float* __restrict__ lnb,
            float* __restrict__ out)
{
    const int cta  = blockIdx.x;
    const int b    = cta >> 3;
    const int k    = cta & 7;
    const int tid  = threadIdx.x;
    const int wid  = tid >> 5;
    const int lane = tid & 31;

    __shared__ float2 s_red[NWARP];
    __shared__ float  s_cm, s_cr;
    __shared__ __align__(16) float s_h[DIM];

    const __half* W0 = d_whh0h + (size_t)b * G4 * DIM;
    const __half* W1 = d_w1h   + (size_t)b * G4 * DIM;
    volatile unsigned* bar = &d_bar[b * 32];
    unsigned epoch = 0;

    const int row0 = k * ROWS_PER_CTA + wid * ROWS_PER_WARP;

    // per-thread LN params for both layers (d = tid)
    const float gw0 = __ldg(lnw + tid),       gb0 = __ldg(lnb + tid);
    const float gw1 = __ldg(lnw + DIM + tid), gb1 = __ldg(lnb + DIM + tid);

    float creg = 0.f;          // c[d=tid], redundant copy per CTA
    s_h[tid] = 0.f;            // h, redundant copy per CTA
    __syncthreads();

    for (int t = 0; t < SEQ; t++) {
#pragma unroll
        for (int l = 0; l < 2; l++) {
            const __half* W   = (l == 0) ? W0 : W1;
            const float*  add = (l == 0) ? (d_pre0 + ((size_t)b * SEQ + t) * G4)
                                         : (d_bias1 + (size_t)b * G4);
            float* gates = d_gates + (size_t)l * BATCH * G4 + (size_t)b * G4;

            // ---- matvec: gates[j] = add[j] + W[j,:] . h (h from shared) ----
            float hf[16];
            {
                const float4* hp = (const float4*)s_h;
                float4 v0 = hp[2*lane], v1 = hp[2*lane+1];
                float4 v2 = hp[64+2*lane], v3 = hp[64+2*lane+1];
                hf[0]=v0.x; hf[1]=v0.y; hf[2]=v0.z;  hf[3]=v0.w;
                hf[4]=v1.x; hf[5]=v1.y; hf[6]=v1.z;  hf[7]=v1.w;
                hf[8]=v2.x; hf[9]=v2.y; hf[10]=v2.z; hf[11]=v2.w;
                hf[12]=v3.x; hf[13]=v3.y; hf[14]=v3.z; hf[15]=v3.w;
            }
            float s1 = 0.f, s2 = 0.f;
            const uint4* wrow = (const uint4*)(W + (size_t)row0 * DIM);  // 64 uint4/row
#pragma unroll 2
            for (int r = 0; r < ROWS_PER_WARP; r += 2) {
                const uint4* w0p = wrow + (size_t)r * 64;
                const uint4* w1p = wrow + (size_t)(r + 1) * 64;
                uint4 a0 = __ldg(w0p + lane);
                uint4 a1 = __ldg(w0p + 32 + lane);
                uint4 b0 = __ldg(w1p + lane);
                uint4 b1 = __ldg(w1p + 32 + lane);
                float accA = dot16(a0, a1, hf);
                float accB = dot16(b0, b1, hf);
#pragma unroll
                for (int o = 16; o > 0; o >>= 1) {
                    accA += __shfl_down_sync(0xffffffffu, accA, o);
                    accB += __shfl_down_sync(0xffffffffu, accB, o);
                }
                if (lane == 0) {
                    float g0 = accA + __ldg(add + row0 + r);
                    float g1 = accB + __ldg(add + row0 + r + 1);
                    gates[row0 + r]     = g0;
                    gates[row0 + r + 1] = g1;
                    s1 += g0 + g1;
                    s2 += fmaf(g0, g0, g1 * g1);
                }
            }
            if (lane == 0) s_red[wid] = make_float2(s1, s2);
            __syncthreads();
            if (tid == 0) {
                float a = 0.f, c = 0.f;
#pragma unroll
                for (int i = 0; i < NWARP; i++) { a += s_red[i].x; c += s_red[i].y; }
                d_gstat[l * NCTA + cta] = make_float2(a, c);
            }
            group_barrier(bar, &epoch, tid);

            // ---- pointwise (redundant per CTA; c in reg, h in shared) ----
            {
                const int d = tid;
                const float gw = (l == 0) ? gw0 : gw1;
                const float gb = (l == 0) ? gb0 : gb1;
                float m_[4], r_[4];
#pragma unroll
                for (int q = 0; q < 4; q++) {
                    float2 p0 = __ldcg(&d_gstat[l * NCTA + b * 8 + 2*q]);
                    float2 p1 = __ldcg(&d_gstat[l * NCTA + b * 8 + 2*q + 1]);
                    float s  = p0.x + p1.x;
                    float ss = p0.y + p1.y;
                    float m  = s * (1.f / 512.f);
                    float v  = fmaf(-m, m, ss * (1.f / 512.f));
                    m_[q] = m;
                    r_[q] = rsqrtf(v + LN_EPS);
                }
                float xi = __ldcg(gates + d);
                float xf = __ldcg(gates + 512 + d);
                float xg = __ldcg(gates + 1024 + d);
                float xo = __ldcg(gates + 1536 + d);
                float iv = sigmoidf_(fmaf((xi - m_[0]) * r_[0], gw, gb));
                float fv = sigmoidf_(fmaf((xf - m_[1]) * r_[1], gw, gb));
                float gv = tanhf(    fmaf((xg - m_[2]) * r_[2], gw, gb));
                float ov = sigmoidf_(fmaf((xo - m_[3]) * r_[3], gw, gb));
                float cn = fmaf(fv, creg, iv * gv);
                creg = cn;

                // block-local LN(c) stats over 512 elems
                float a = cn, c2 = cn * cn;
#pragma unroll
                for (int o = 16; o > 0; o >>= 1) {
                    a  += __shfl_down_sync(0xffffffffu, a, o);
                    c2 += __shfl_down_sync(0xffffffffu, c2, o);
                }
                if (lane == 0) s_red[wid] = make_float2(a, c2);
                __syncthreads();
                if (tid == 0) {
                    float sa = 0.f, sb = 0.f;
#pragma unroll
                    for (int i = 0; i < NWARP; i++) { sa += s_red[i].x; sb += s_red[i].y; }
                    float m = sa * (1.f / 512.f);
                    float v = fmaf(-m, m, sb * (1.f / 512.f));
                    s_cm = m;
                    s_cr = rsqrtf(v + LN_EPS);
                }
                __syncthreads();
                float hv = ov * tanhf(fmaf((cn - s_cm) * s_cr, gw, gb));
                s_h[d] = hv;
                if (l == 1 && k == 0)
                    out[((size_t)b * SEQ + t) * DIM + d] = hv;
                __syncthreads();   // s_h ready before next matvec
            }
        }
    }
}

extern "C" void kernel_launch(void* const* d_in, const int* in_sizes, int n_in,
                              void* d_out, int out_size) {
    const float* x    = (const float*)d_in[0];
    const float* wih0 = (const float*)d_in[1];
    const float* whh0 = (const float*)d_in[2];
    const float* bih0 = (const float*)d_in[3];
    const float* bhh0 = (const float*)d_in[4];
    const float* wih1 = (const float*)d_in[5];
    const float* whh1 = (const float*)d_in[6];
    const float* bih1 = (const float*)d_in[7];
    const float* bhh1 = (const float*)d_in[8];
    const float* ln_w = (const float*)d_in[9];
    const float* ln_b = (const float*)d_in[10];
    float* out = (float*)d_out;

    prep_kernel<<<1024, 256>>>(whh0, wih1, whh1, bih1, bhh1);
    gemm_pre0<<<dim3(32, 16), 256>>>(x, wih0, bih0, bhh0);
    lstm_kernel<<<NCTA, TPB>>>(ln_w, ln_b, out);
}

// round 3
// speedup vs baseline: 1.1230x; 1.1230x over previous
#include <cuda_runtime.h>
#include <cuda_fp16.h>
#include <cstdint>

#define BATCH 16
#define SEQ   256
#define DIM   512
#define G4    2048
#define LN_EPS 1e-5f

#define GROUPS 8                  // CTAs per batch
#define NCTA  (BATCH*GROUPS)      // 128
#define TPB   512
#define ROWS_PER_CTA 256
#define ROWS_PER_WARP 16
#define NWARP 16

// SMEM-resident weight rows per warp: 8 from layer0 + 6 from layer1 = 14 rows (14 KB)
#define SR_L0 8
#define SR_L1 6
#define SM_ROWS_PER_WARP (SR_L0 + SR_L1)          // 14
#define SM_ROWS (NWARP * SM_ROWS_PER_WARP)        // 224 rows = 224 KB
#define SMEM_W_BYTES (SM_ROWS * DIM * 2)          // 229376
#define SMEM_TOTAL (SMEM_W_BYTES + DIM*4 + NWARP*8 + 16)  // +s_h +s_red +cm/cr

// ---------------- static device scratch (no allocation allowed) ----------------
__device__ __half  d_whh0h[(size_t)BATCH*G4*DIM];   // 32 MB fp16
__device__ __half  d_w1h  [(size_t)BATCH*G4*DIM];   // 32 MB fp16 (wih1+whh1)
__device__ float   d_pre0 [(size_t)BATCH*SEQ*G4];   // 32 MB: wih0@x + bih0 + bhh0
__device__ float   d_bias1[BATCH*G4];
__device__ float   d_gates[2*BATCH*G4];             // double-buffered per layer
__device__ float2  d_gstat[2*NCTA];                 // per-CTA (sum, sumsq), per layer
__device__ unsigned d_bar [BATCH*32];               // per-batch barrier counters (padded)

// ---------------- prep: fp16 convert, merge layer-1 weights, fold biases, reset ----
__global__ void prep_kernel(const float* __restrict__ whh0,
                            const float* __restrict__ wih1,
                            const float* __restrict__ whh1,
                            const float* __restrict__ bih1,
                            const float* __restrict__ bhh1)
{
    int idx0 = blockIdx.x * blockDim.x + threadIdx.x;
    int stride = gridDim.x * blockDim.x;
    const size_t NW = (size_t)BATCH * G4 * DIM;
    for (size_t i = idx0; i < NW; i += stride) {
        d_whh0h[i] = __float2half_rn(whh0[i]);
        d_w1h[i]   = __float2half_rn(wih1[i] + whh1[i]);
    }
    if (idx0 < BATCH * G4) d_bias1[idx0] = bih1[idx0] + bhh1[idx0];
    if (idx0 < BATCH * 32) d_bar[idx0] = 0u;
}

// ---- SGEMM: d_pre0[b][t][j] = sum_d wih0[b][j][d]*x[b][t][d] + bih0[b][j] + bhh0[b][j]
__global__ void __launch_bounds__(256) gemm_pre0(const float* __restrict__ x,
                                                 const float* __restrict__ wih0,
                                                 const float* __restrict__ bih0,
                                                 const float* __restrict__ bhh0)
{
    __shared__ float As[16][132];
    __shared__ float Bs[16][132];
    const int b  = blockIdx.y;
    const int mt = blockIdx.x & 15;   // j tile (2048/128 = 16)
    const int nt = blockIdx.x >> 4;   // t tile (256/128  = 2)
    const float* A = wih0 + ((size_t)b * G4  + (size_t)mt * 128) * DIM;
    const float* B = x    + ((size_t)b * SEQ + (size_t)nt * 128) * DIM;
    const int tid = threadIdx.x;
    const int tr = tid & 15;          // j-frag selector
    const int tc = tid >> 4;          // t-frag selector

    float acc[8][8];
#pragma unroll
    for (int i = 0; i < 8; i++)
#pragma unroll
        for (int j = 0; j < 8; j++) acc[i][j] = 0.f;

    for (int k0 = 0; k0 < DIM; k0 += 16) {
        __syncthreads();
#pragma unroll
        for (int p = 0; p < 2; p++) {
            int fid = tid + p * 256;
            int row = fid >> 2;
            int kq  = fid & 3;
            float4 va = *(const float4*)(A + (size_t)row * DIM + k0 + kq * 4);
            As[kq*4+0][row] = va.x; As[kq*4+1][row] = va.y;
            As[kq*4+2][row] = va.z; As[kq*4+3][row] = va.w;
            float4 vb = *(const float4*)(B + (size_t)row * DIM + k0 + kq * 4);
            Bs[kq*4+0][row] = vb.x; Bs[kq*4+1][row] = vb.y;
            Bs[kq*4+2][row] = vb.z; Bs[kq*4+3][row] = vb.w;
        }
        __syncthreads();
#pragma unroll
        for (int kk = 0; kk < 16; kk++) {
            float af[8], bf[8];
#pragma unroll
            for (int i = 0; i < 4; i++) {
                af[i]   = As[kk][tr*4 + i];
                af[4+i] = As[kk][64 + tr*4 + i];
                bf[i]   = Bs[kk][tc*4 + i];
                bf[4+i] = Bs[kk][64 + tc*4 + i];
            }
#pragma unroll
            for (int i = 0; i < 8; i++)
#pragma unroll
                for (int j = 0; j < 8; j++)
                    acc[i][j] = fmaf(af[i], bf[j], acc[i][j]);
        }
    }

    float biasv[8];
#pragma unroll
    for (int i = 0; i < 8; i++) {
        int j = mt * 128 + ((i < 4) ? (tr*4 + i) : (64 + tr*4 + (i - 4)));
        biasv[i] = bih0[b * G4 + j] + bhh0[b * G4 + j];
    }
#pragma unroll
    for (int jj = 0; jj < 8; jj++) {
        int t = nt * 128 + ((jj < 4) ? (tc*4 + jj) : (64 + tc*4 + (jj - 4)));
        float* dst = &d_pre0[((size_t)b * SEQ + t) * G4 + mt * 128];
        float4 v0, v1;
        v0.x = acc[0][jj] + biasv[0]; v0.y = acc[1][jj] + biasv[1];
        v0.z = acc[2][jj] + biasv[2]; v0.w = acc[3][jj] + biasv[3];
        v1.x = acc[4][jj] + biasv[4]; v1.y = acc[5][jj] + biasv[5];
        v1.z = acc[6][jj] + biasv[6]; v1.w = acc[7][jj] + biasv[7];
        *(float4*)(dst + tr * 4)      = v0;
        *(float4*)(dst + 64 + tr * 4) = v1;
    }
}

// ---------------- persistent LSTM kernel ----------------
__device__ __forceinline__ float sigmoidf_(float x) {
    return __fdividef(1.f, 1.f + __expf(-x));
}

__device__ __forceinline__ float dot16(uint4 wa, uint4 wb, const float* hf) {
    float acc = 0.f;
    float2 f;
    f = __half22float2(*reinterpret_cast<__half2*>(&wa.x)); acc = fmaf(f.x, hf[0],  acc); acc = fmaf(f.y, hf[1],  acc);
    f = __half22float2(*reinterpret_cast<__half2*>(&wa.y)); acc = fmaf(f.x, hf[2],  acc); acc = fmaf(f.y, hf[3],  acc);
    f = __half22float2(*reinterpret_cast<__half2*>(&wa.z)); acc = fmaf(f.x, hf[4],  acc); acc = fmaf(f.y, hf[5],  acc);
    f = __half22float2(*reinterpret_cast<__half2*>(&wa.w)); acc = fmaf(f.x, hf[6],  acc); acc = fmaf(f.y, hf[7],  acc);
    f = __half22float2(*reinterpret_cast<__half2*>(&wb.x)); acc = fmaf(f.x, hf[8],  acc); acc = fmaf(f.y, hf[9],  acc);
    f = __half22float2(*reinterpret_cast<__half2*>(&wb.y)); acc = fmaf(f.x, hf[10], acc); acc = fmaf(f.y, hf[11], acc);
    f = __half22float2(*reinterpret_cast<__half2*>(&wb.z)); acc = fmaf(f.x, hf[12], acc); acc = fmaf(f.y, hf[13], acc);
    f = __half22float2(*reinterpret_cast<__half2*>(&wb.w)); acc = fmaf(f.x, hf[14], acc); acc = fmaf(f.y, hf[15], acc);
    return acc;
}

// 8-CTA per-batch barrier (release/acquire via L2 atomics)
__device__ __forceinline__ void group_barrier(volatile unsigned* bar, unsigned* epoch, int tid) {
    __syncthreads();
    *epoch += GROUPS;
    unsigned target = *epoch;
    if (tid == 0) {
        __threadfence();
        atomicAdd((unsigned*)bar, 1u);
        while (*bar < target) { }
        __threadfence();
    }
    __syncthreads();
}

__global__ void __launch_bounds__(TPB, 1)
lstm_kernel(const float* __restrict__ lnw, const float* __restrict__ lnb,
            float* __restrict__ out)
{
    extern __shared__ __align__(16) unsigned char smem_raw[];
    __half*  s_w   = (__half*)smem_raw;                                  // 224 KB
    float*   s_h   = (float*)(smem_raw + SMEM_W_BYTES);                  // 2 KB
    float2*  s_red = (float2*)(smem_raw + SMEM_W_BYTES + DIM * 4);       // 128 B
    float*   s_c   = (float*)(smem_raw + SMEM_W_BYTES + DIM * 4 + NWARP * 8); // cm, cr

    const int cta  = blockIdx.x;
    const int b    = cta >> 3;
    const int k    = cta & 7;
    const int tid  = threadIdx.x;
    const int wid  = tid >> 5;
    const int lane = tid & 31;

    const __half* W0 = d_whh0h + (size_t)b * G4 * DIM;
    const __half* W1 = d_w1h   + (size_t)b * G4 * DIM;
    volatile unsigned* bar = &d_bar[b * 32];
    unsigned epoch = 0;

    const int row0 = k * ROWS_PER_CTA + wid * ROWS_PER_WARP;

    // ---- fill SMEM weight cache: per warp, rows [0,8) of L0 and [0,6) of L1 ----
    {
        const int nU4 = SM_ROWS * (DIM / 8);   // 14336 uint4
        for (int i = tid; i < nU4; i += TPB) {
            int slot = i >> 6;                 // row slot (64 uint4 per row)
            int col  = i & 63;
            int w    = slot / SM_ROWS_PER_WARP;
            int rem  = slot % SM_ROWS_PER_WARP;
            int l    = (rem < SR_L0) ? 0 : 1;
            int r    = (rem < SR_L0) ? rem : (rem - SR_L0);
            const __half* W = (l == 0) ? W0 : W1;
            size_t grow = (size_t)(k * ROWS_PER_CTA + w * ROWS_PER_WARP + r) * DIM;
            ((uint4*)s_w)[i] = ((const uint4*)(W + grow))[col];
        }
    }

    // per-thread LN params for both layers (d = tid)
    const float gw0 = __ldg(lnw + tid),       gb0 = __ldg(lnb + tid);
    const float gw1 = __ldg(lnw + DIM + tid), gb1 = __ldg(lnb + DIM + tid);

    float creg = 0.f;          // c[d=tid], redundant copy per CTA
    s_h[tid] = 0.f;            // h, redundant copy per CTA
    __syncthreads();

    for (int t = 0; t < SEQ; t++) {
#pragma unroll
        for (int l = 0; l < 2; l++) {
            const __half* W   = (l == 0) ? W0 : W1;
            const float*  add = (l == 0) ? (d_pre0 + ((size_t)b * SEQ + t) * G4)
                                         : (d_bias1 + (size_t)b * G4);
            float* gates = d_gates + (size_t)l * BATCH * G4 + (size_t)b * G4;
            const int SR    = (l == 0) ? SR_L0 : SR_L1;
            const int sbase = wid * SM_ROWS_PER_WARP + ((l == 0) ? 0 : SR_L0);

            // ---- load h into registers (16 elems per lane) ----
            float hf[16];
            {
                const float4* hp = (const float4*)s_h;
                float4 v0 = hp[2*lane], v1 = hp[2*lane+1];
                float4 v2 = hp[64+2*lane], v3 = hp[64+2*lane+1];
                hf[0]=v0.x; hf[1]=v0.y; hf[2]=v0.z;  hf[3]=v0.w;
                hf[4]=v1.x; hf[5]=v1.y; hf[6]=v1.z;  hf[7]=v1.w;
                hf[8]=v2.x; hf[9]=v2.y; hf[10]=v2.z; hf[11]=v2.w;
                hf[12]=v3.x; hf[13]=v3.y; hf[14]=v3.z; hf[15]=v3.w;
            }
            float s1 = 0.f, s2 = 0.f;
            const uint4* wrow = (const uint4*)(W + (size_t)row0 * DIM);  // 64 uint4/row

            // ---- SMEM-resident rows ----
#pragma unroll
            for (int r = 0; r < ((l == 0) ? SR_L0 : SR_L1); r += 2) {
                const uint4* w0p = (const uint4*)(s_w + (size_t)(sbase + r) * DIM);
                const uint4* w1p = (const uint4*)(s_w + (size_t)(sbase + r + 1) * DIM);
                uint4 a0 = w0p[lane];
                uint4 a1 = w0p[32 + lane];
                uint4 b0 = w1p[lane];
                uint4 b1 = w1p[32 + lane];
                float accA = dot16(a0, a1, hf);
                float accB = dot16(b0, b1, hf);
#pragma unroll
                for (int o = 16; o > 0; o >>= 1) {
                    accA += __shfl_down_sync(0xffffffffu, accA, o);
                    accB += __shfl_down_sync(0xffffffffu, accB, o);
                }
                if (lane == 0) {
                    float g0 = accA + __ldg(add + row0 + r);
                    float g1 = accB + __ldg(add + row0 + r + 1);
                    gates[row0 + r]     = g0;
                    gates[row0 + r + 1] = g1;
                    s1 += g0 + g1;
                    s2 += fmaf(g0, g0, g1 * g1);
                }
            }
            // ---- L2-streamed rows ----
#pragma unroll 2
            for (int r = ((l == 0) ? SR_L0 : SR_L1); r < ROWS_PER_WARP; r += 2) {
                const uint4* w0p = wrow + (size_t)r * 64;
                const uint4* w1p = wrow + (size_t)(r + 1) * 64;
                uint4 a0 = __ldcg(w0p + lane);
                uint4 a1 = __ldcg(w0p + 32 + lane);
                uint4 b0 = __ldcg(w1p + lane);
                uint4 b1 = __ldcg(w1p + 32 + lane);
                float accA = dot16(a0, a1, hf);
                float accB = dot16(b0, b1, hf);
#pragma unroll
                for (int o = 16; o > 0; o >>= 1) {
                    accA += __shfl_down_sync(0xffffffffu, accA, o);
                    accB += __shfl_down_sync(0xffffffffu, accB, o);
                }
                if (lane == 0) {
                    float g0 = accA + __ldg(add + row0 + r);
                    float g1 = accB + __ldg(add + row0 + r + 1);
                    gates[row0 + r]     = g0;
                    gates[row0 + r + 1] = g1;
                    s1 += g0 + g1;
                    s2 += fmaf(g0, g0, g1 * g1);
                }
            }
            if (lane == 0) s_red[wid] = make_float2(s1, s2);
            __syncthreads();
            if (tid == 0) {
                float a = 0.f, c = 0.f;
#pragma unroll
                for (int i = 0; i < NWARP; i++) { a += s_red[i].x; c += s_red[i].y; }
                d_gstat[l * NCTA + cta] = make_float2(a, c);
            }
            group_barrier(bar, &epoch, tid);

            // ---- pointwise (redundant per CTA; c in reg, h in shared) ----
            {
                const int d = tid;
                const float gw = (l == 0) ? gw0 : gw1;
                const float gb = (l == 0) ? gb0 : gb1;
                float m_[4], r_[4];
#pragma unroll
                for (int q = 0; q < 4; q++) {
                    float2 p0 = __ldcg(&d_gstat[l * NCTA + b * 8 + 2*q]);
                    float2 p1 = __ldcg(&d_gstat[l * NCTA + b * 8 + 2*q + 1]);
                    float s  = p0.x + p1.x;
                    float ss = p0.y + p1.y;
                    float m  = s * (1.f / 512.f);
                    float v  = fmaf(-m, m, ss * (1.f / 512.f));
                    m_[q] = m;
                    r_[q] = rsqrtf(v + LN_EPS);
                }
                float xi = __ldcg(gates + d);
                float xf = __ldcg(gates + 512 + d);
                float xg = __ldcg(gates + 1024 + d);
                float xo = __ldcg(gates + 1536 + d);
                float iv = sigmoidf_(fmaf((xi - m_[0]) * r_[0], gw, gb));
                float fv = sigmoidf_(fmaf((xf - m_[1]) * r_[1], gw, gb));
                float gv = tanhf(    fmaf((xg - m_[2]) * r_[2], gw, gb));
                float ov = sigmoidf_(fmaf((xo - m_[3]) * r_[3], gw, gb));
                float cn = fmaf(fv, creg, iv * gv);
                creg = cn;

                // block-local LN(c) stats over 512 elems
                float a = cn, c2 = cn * cn;
#pragma unroll
                for (int o = 16; o > 0; o >>= 1) {
                    a  += __shfl_down_sync(0xffffffffu, a, o);
                    c2 += __shfl_down_sync(0xffffffffu, c2, o);
                }
                if (lane == 0) s_red[wid] = make_float2(a, c2);
                __syncthreads();
                if (tid == 0) {
                    float sa = 0.f, sb = 0.f;
#pragma unroll
                    for (int i = 0; i < NWARP; i++) { sa += s_red[i].x; sb += s_red[i].y; }
                    float m = sa * (1.f / 512.f);
                    float v = fmaf(-m, m, sb * (1.f / 512.f));
                    s_c[0] = m;
                    s_c[1] = rsqrtf(v + LN_EPS);
                }
                __syncthreads();
                float hv = ov * tanhf(fmaf((cn - s_c[0]) * s_c[1], gw, gb));
                s_h[d] = hv;
                if (l == 1 && k == 0)
                    out[((size_t)b * SEQ + t) * DIM + d] = hv;
                __syncthreads();   // s_h ready before next matvec
            }
        }
    }
}

extern "C" void kernel_launch(void* const* d_in, const int* in_sizes, int n_in,
                              void* d_out, int out_size) {
    const float* x    = (const float*)d_in[0];
    const float* wih0 = (const float*)d_in[1];
    const float* whh0 = (const float*)d_in[2];
    const float* bih0 = (const float*)d_in[3];
    const float* bhh0 = (const float*)d_in[4];
    const float* wih1 = (const float*)d_in[5];
    const float* whh1 = (const float*)d_in[6];
    const float* bih1 = (const float*)d_in[7];
    const float* bhh1 = (const float*)d_in[8];
    const float* ln_w = (const float*)d_in[9];
    const float* ln_b = (const float*)d_in[10];
    float* out = (float*)d_out;

    cudaFuncSetAttribute(lstm_kernel, cudaFuncAttributeMaxDynamicSharedMemorySize,
                         SMEM_TOTAL);

    prep_kernel<<<1024, 256>>>(whh0, wih1, whh1, bih1, bhh1);
    gemm_pre0<<<dim3(32, 16), 256>>>(x, wih0, bih0, bhh0);
    lstm_kernel<<<NCTA, TPB, SMEM_TOTAL>>>(ln_w, ln_b, out);
}